// round 3
// baseline (speedup 1.0000x reference)
#include <cuda_runtime.h>
#include <cuda_fp16.h>
#include <cstdint>
#include <math.h>

// ============================================================================
// VectorQuantizer (N=262144, K=1024, D=64) for .target sm_100 (no tcgen05).
// mma.sync.m16n8k16 f16 GEMM computes d = |c|^2+128 - 2 x.c directly
// (B = -2c in f16, accumulator initialized with |c|^2+128).
// Branchless packed-key top-3 per lane -> exact fp32 re-rank of survivors
// using the reference distance formula. Fused losses/histogram/perplexity.
// ============================================================================

constexpr int D_DIM   = 64;
constexpr int K_CODES = 1024;
constexpr int TILE_M  = 128;
constexpr int N_ROWS  = 262144;
constexpr int N_TILES = N_ROWS / TILE_M;     // 2048
constexpr int NCH     = 64;                  // codes per inner chunk
constexpr int CHUNKS  = K_CODES / NCH;       // 16
constexpr int THREADS = 256;                 // 8 warps, 16 rows each
constexpr int QELEMS  = N_ROWS * D_DIM;      // 16777216

// ---- dynamic smem layout (bytes) ----
constexpr int BST      = 144;                        // f16 B row pitch (72 halves)
constexpr int OFF_B    = 0;                          // -2c f16: 1024 x 144B
constexpr int AST      = 144;                        // f16 A row pitch
constexpr int OFF_A    = OFF_B + K_CODES * BST;      // 147456: X f16 128 x 144B
constexpr int OFF_CN   = OFF_A + TILE_M * AST;       // 165888: |c|^2 fp32[1024]
constexpr int OFF_X    = OFF_CN + K_CODES * 4;       // 169984: X fp32 128 x 68
constexpr int XST      = 68;
constexpr int OFF_HIST = OFF_X + TILE_M * XST * 4;   // 204800: int[1024]
constexpr int OFF_CAND = OFF_HIST + K_CODES * 4;     // 208896: 12 keys/row
constexpr int OFF_BK   = OFF_CAND + TILE_M * 12 * 4; // 215040: best idx/row
constexpr int OFF_RED  = OFF_BK + TILE_M * 4;        // 215552: reduce scratch
constexpr int SMEM_TOTAL = OFF_RED + 64;             // 215616 B

// ---- device globals ----
__device__ __half g_cbm2[K_CODES * D_DIM];   // -2 * codebook, f16
__device__ float  g_cn[K_CODES];             // |c|^2 fp32
__device__ float  g_sqsum;
__device__ int    g_counts[K_CODES];

// ---- PTX helpers (sm_80-level only) ----
static __device__ __forceinline__ uint32_t smem_u32(const void* p) {
    uint32_t a;
    asm("{ .reg .u64 t; cvta.to.shared.u64 t, %1; cvt.u32.u64 %0, t; }" : "=r"(a) : "l"(p));
    return a;
}

#define LDSM4(r, addr) \
    asm volatile("ldmatrix.sync.aligned.m8n8.x4.shared.b16 {%0,%1,%2,%3}, [%4];" \
        : "=r"((r)[0]), "=r"((r)[1]), "=r"((r)[2]), "=r"((r)[3]) : "r"(addr))

#define MMA16816(d, a, b0_, b1_) \
    asm volatile("mma.sync.aligned.m16n8k16.row.col.f32.f16.f16.f32 " \
        "{%0,%1,%2,%3}, {%4,%5,%6,%7}, {%8,%9}, {%0,%1,%2,%3};" \
        : "+f"((d)[0]), "+f"((d)[1]), "+f"((d)[2]), "+f"((d)[3]) \
        : "r"((a)[0]), "r"((a)[1]), "r"((a)[2]), "r"((a)[3]), "r"(b0_), "r"(b1_))

// branchless top-3 insert (ascending keys k0<=k1<=k2)
#define INS3(key, k0, k1, k2) do {                      \
    uint32_t t0_ = max(key, k0); k0 = min(key, k0);     \
    uint32_t t1_ = max(t0_, k1); k1 = min(t0_, k1);     \
    k2 = min(t1_, k2);                                  \
} while (0)

// ============================================================================
// Kernel 0: prep — f16(-2c), |c|^2, zero accumulators.
// ============================================================================
__global__ void vq_prep(const float* __restrict__ cb) {
    int k = blockIdx.x * blockDim.x + threadIdx.x;
    if (k < K_CODES) {
        float s = 0.f;
#pragma unroll
        for (int i = 0; i < D_DIM; i++) {
            float v = cb[k * D_DIM + i];
            s = fmaf(v, v, s);
            g_cbm2[k * D_DIM + i] = __float2half_rn(-2.0f * v);
        }
        g_cn[k] = s;
        g_counts[k] = 0;
        if (k == 0) g_sqsum = 0.f;
    }
}

// ============================================================================
// Kernel 1: persistent main kernel
// ============================================================================
__global__ void __launch_bounds__(THREADS, 1)
vq_main(const float* __restrict__ x, const float* __restrict__ cbf,
        float* __restrict__ outq, float* __restrict__ outtok) {
    extern __shared__ char smem[];
    const uint32_t sb = smem_u32(smem);
    const int tid = threadIdx.x;
    const int wid = tid >> 5;
    const int lid = tid & 31;
    const int g   = lid >> 2;        // fragment row group (0..7)
    const int t   = lid & 3;         // fragment col pair (0..3)

    // ---- one-time staging: B (-2c f16, padded pitch) + |c|^2 + hist zero ----
    {
        const uint4* bsrc = reinterpret_cast<const uint4*>(g_cbm2);
        for (int i = tid; i < (K_CODES * D_DIM) / 8; i += THREADS) {  // 8192 uint4
            uint4 v = bsrc[i];
            int row = i >> 3, c8 = i & 7;
            *reinterpret_cast<uint4*>(smem + OFF_B + row * BST + c8 * 16) = v;
        }
        float* cns = reinterpret_cast<float*>(smem + OFF_CN);
        int*   hist = reinterpret_cast<int*>(smem + OFF_HIST);
        for (int i = tid; i < K_CODES; i += THREADS) { cns[i] = g_cn[i]; hist[i] = 0; }
    }
    __syncthreads();

    const float*  cns  = reinterpret_cast<const float*>(smem + OFF_CN);
    const float2* cns2 = reinterpret_cast<const float2*>(smem + OFF_CN);
    int*      hist  = reinterpret_cast<int*>(smem + OFF_HIST);
    uint32_t* cand  = reinterpret_cast<uint32_t*>(smem + OFF_CAND);
    int*      bkp   = reinterpret_cast<int*>(smem + OFF_BK);
    float*    redp  = reinterpret_cast<float*>(smem + OFF_RED);

    // ldmatrix per-lane address bases
    const int mat = lid >> 3, r = lid & 7;
    const uint32_t abase = sb + OFF_A + (uint32_t)(wid * 16 + ((mat & 1) << 3) + r) * AST
                         + (uint32_t)(((mat >> 1) << 3) * 2);
    const uint32_t bbase = sb + OFF_B + (uint32_t)(((mat >> 1) << 3) + r) * BST
                         + (uint32_t)(((mat & 1) << 3) * 2);

    float loss_acc = 0.f;

    for (int tile = blockIdx.x; tile < N_TILES; tile += gridDim.x) {
        // ---- stage X tile: fp32 copy + f16 copy (padded pitch) ----
        const float4* xin = reinterpret_cast<const float4*>(x + (size_t)tile * TILE_M * D_DIM);
#pragma unroll
        for (int j = 0; j < 8; j++) {
            int i4 = tid + j * THREADS;              // 2048 float4 per tile
            float4 v = xin[i4];
            int row = i4 >> 4, c4 = i4 & 15;
            *reinterpret_cast<float4*>(smem + OFF_X + (row * XST + c4 * 4) * 4) = v;
            __half2 h0 = __floats2half2_rn(v.x, v.y);
            __half2 h1 = __floats2half2_rn(v.z, v.w);
            uint2 u;
            u.x = *reinterpret_cast<uint32_t*>(&h0);
            u.y = *reinterpret_cast<uint32_t*>(&h1);
            *reinterpret_cast<uint2*>(smem + OFF_A + row * AST + c4 * 8) = u;
        }
        __syncthreads();

        // ---- A fragments for this warp's 16 rows (all 4 k-steps) ----
        uint32_t af[4][4];
#pragma unroll
        for (int ks = 0; ks < 4; ks++) LDSM4(af[ks], abase + ks * 32);

        // ---- stream all 1024 codes; keep top-3 packed keys per row-slot ----
        uint32_t s0k0 = ~0u, s0k1 = ~0u, s0k2 = ~0u;   // row = wid*16+g
        uint32_t s1k0 = ~0u, s1k1 = ~0u, s1k2 = ~0u;   // row = wid*16+g+8
#pragma unroll 1
        for (int c = 0; c < CHUNKS; c++) {
            const int cb0 = c * NCH;
            float cnr[16];
#pragma unroll
            for (int jj = 0; jj < 8; jj++) {
                float2 p = cns2[(cb0 >> 1) + jj * 4 + t];
                cnr[2 * jj]     = p.x + 128.0f;
                cnr[2 * jj + 1] = p.y + 128.0f;
            }
            float acc[32];
#pragma unroll
            for (int j = 0; j < 8; j++) {
                acc[4 * j + 0] = cnr[2 * j];
                acc[4 * j + 1] = cnr[2 * j + 1];
                acc[4 * j + 2] = cnr[2 * j];
                acc[4 * j + 3] = cnr[2 * j + 1];
            }
#pragma unroll
            for (int ks = 0; ks < 4; ks++) {
                uint32_t b[16];
#pragma unroll
                for (int p = 0; p < 4; p++)
                    LDSM4(b + 4 * p, bbase + (uint32_t)(cb0 + p * 16) * BST + ks * 32);
#pragma unroll
                for (int j = 0; j < 8; j++)
                    MMA16816(acc + 4 * j, af[ks],
                             b[4 * (j >> 1) + 2 * (j & 1)],
                             b[4 * (j >> 1) + 2 * (j & 1) + 1]);
            }
            // fold 32 distances (all positive) into packed-key top-3 chains
            const int codebase = cb0 + 2 * t;
#pragma unroll
            for (int j = 0; j < 8; j++) {
                const uint32_t c0 = (uint32_t)(codebase + 8 * j);
                uint32_t k00 = (__float_as_uint(acc[4 * j + 0]) & 0xFFFFFC00u) | c0;
                uint32_t k01 = (__float_as_uint(acc[4 * j + 1]) & 0xFFFFFC00u) | (c0 + 1);
                uint32_t k10 = (__float_as_uint(acc[4 * j + 2]) & 0xFFFFFC00u) | c0;
                uint32_t k11 = (__float_as_uint(acc[4 * j + 3]) & 0xFFFFFC00u) | (c0 + 1);
                INS3(k00, s0k0, s0k1, s0k2);
                INS3(k01, s0k0, s0k1, s0k2);
                INS3(k10, s1k0, s1k1, s1k2);
                INS3(k11, s1k0, s1k1, s1k2);
            }
        }
        // ---- publish 12 candidates per row ----
        {
            int row0 = wid * 16 + g, row1 = row0 + 8, t3 = t * 3;
            cand[row0 * 12 + t3 + 0] = s0k0;
            cand[row0 * 12 + t3 + 1] = s0k1;
            cand[row0 * 12 + t3 + 2] = s0k2;
            cand[row1 * 12 + t3 + 0] = s1k0;
            cand[row1 * 12 + t3 + 1] = s1k1;
            cand[row1 * 12 + t3 + 2] = s1k2;
        }
        __syncthreads();

        // ---- exact fp32 re-rank of survivors (reference formula) ----
        if (tid < TILE_M) {
            const int row = tid;
            float xr[64];
            const float4* xs = reinterpret_cast<const float4*>(smem + OFF_X + row * XST * 4);
#pragma unroll
            for (int j = 0; j < 16; j++) {
                float4 v = xs[j];
                xr[4 * j + 0] = v.x; xr[4 * j + 1] = v.y;
                xr[4 * j + 2] = v.z; xr[4 * j + 3] = v.w;
            }
            float xn = 0.f;
#pragma unroll
            for (int i = 0; i < 64; i++) xn = fmaf(xr[i], xr[i], xn);

            uint32_t kmin = ~0u;
#pragma unroll
            for (int j = 0; j < 12; j++) kmin = min(kmin, cand[row * 12 + j]);
            const uint32_t thr = (kmin >> 10) + 3;   // quantum margin >> noise

            float best = 3.4e38f; int bk = 0;
#pragma unroll 1
            for (int j = 0; j < 12; j++) {
                uint32_t key = cand[row * 12 + j];
                if ((key >> 10) <= thr) {
                    int k = (int)(key & 1023u);
                    const float4* cr = reinterpret_cast<const float4*>(cbf + k * D_DIM);
                    float dot = 0.f;                 // serial fma, matches ref closely
#pragma unroll
                    for (int i = 0; i < 16; i++) {
                        float4 cv = cr[i];
                        dot = fmaf(xr[4 * i + 0], cv.x, dot);
                        dot = fmaf(xr[4 * i + 1], cv.y, dot);
                        dot = fmaf(xr[4 * i + 2], cv.z, dot);
                        dot = fmaf(xr[4 * i + 3], cv.w, dot);
                    }
                    float d = (xn + cns[k]) - 2.0f * dot;
                    if (d < best || (d == best && k < bk)) { best = d; bk = k; }
                }
            }
            // exact sum((x-c)^2) of the winner — this is the loss contribution
            {
                const float4* cr = reinterpret_cast<const float4*>(cbf + bk * D_DIM);
                float s0 = 0.f, s1 = 0.f, s2 = 0.f, s3 = 0.f;
#pragma unroll
                for (int i = 0; i < 16; i++) {
                    float4 cv = cr[i];
                    float d0 = xr[4 * i + 0] - cv.x; s0 = fmaf(d0, d0, s0);
                    float d1 = xr[4 * i + 1] - cv.y; s1 = fmaf(d1, d1, s1);
                    float d2 = xr[4 * i + 2] - cv.z; s2 = fmaf(d2, d2, s2);
                    float d3 = xr[4 * i + 3] - cv.w; s3 = fmaf(d3, d3, s3);
                }
                loss_acc += (s0 + s1) + (s2 + s3);
            }
            bkp[row] = bk;
            atomicAdd(&hist[bk], 1);
            outtok[tile * TILE_M + row] = (float)bk;
        }
        __syncthreads();

        // ---- quantized_st = x + (q - x), coalesced ----
#pragma unroll
        for (int j = 0; j < 32; j++) {
            int idx = tid + j * THREADS;             // 8192 elems
            int row = idx >> 6, col = idx & 63;
            int k = bkp[row];
            float q  = cbf[k * D_DIM + col];
            float xv = *reinterpret_cast<const float*>(smem + OFF_X + (row * XST + col) * 4);
            outq[(size_t)tile * (TILE_M * D_DIM) + idx] = xv + (q - xv);
        }
        __syncthreads();   // smem reuse barrier before next tile staging
    }

    // ---- flush: loss partial + histogram ----
    float p = loss_acc;
#pragma unroll
    for (int o = 16; o; o >>= 1) p += __shfl_down_sync(0xFFFFFFFFu, p, o);
    if (lid == 0) redp[wid] = p;
    __syncthreads();
    if (tid == 0) {
        float tot = 0.f;
#pragma unroll
        for (int i = 0; i < 8; i++) tot += redp[i];
        atomicAdd(&g_sqsum, tot);
    }
    for (int i = tid; i < K_CODES; i += THREADS) {
        int c = hist[i];
        if (c) atomicAdd(&g_counts[i], c);
    }
}

// ============================================================================
// Kernel 2: scalars (losses + perplexity)
// ============================================================================
__global__ void vq_finalize(float* __restrict__ out_scalars) {
    __shared__ float red[32];
    int tid = threadIdx.x;                           // 1024 threads
    float p = (float)g_counts[tid] * (1.0f / (float)N_ROWS);
    float t = p * logf(p + 1e-10f);
#pragma unroll
    for (int o = 16; o; o >>= 1) t += __shfl_down_sync(0xFFFFFFFFu, t, o);
    if ((tid & 31) == 0) red[tid >> 5] = t;
    __syncthreads();
    if (tid == 0) {
        float h = 0.f;
#pragma unroll
        for (int i = 0; i < 32; i++) h += red[i];
        float L = g_sqsum * (1.0f / (float)QELEMS);
        out_scalars[0] = 1.25f * L;   // vq_loss
        out_scalars[1] = 0.25f * L;   // commitment_loss
        out_scalars[2] = L;           // codebook_loss
        out_scalars[3] = expf(-h);    // perplexity
    }
}

// ============================================================================
extern "C" void kernel_launch(void* const* d_in, const int* in_sizes, int n_in,
                              void* d_out, int out_size) {
    const float* x  = (const float*)d_in[0];
    const float* cb = (const float*)d_in[1];
    if (n_in >= 2 && in_sizes[0] == K_CODES * D_DIM && in_sizes[1] == QELEMS) {
        const float* tp = x; x = cb; cb = tp;        // defensive: metadata order
    }
    float* out    = (float*)d_out;
    float* outq   = out;                             // 16777216 floats
    float* outtok = out + QELEMS;                    // 262144 floats
    float* outsc  = outtok + N_ROWS;                 // 4 scalars

    cudaFuncSetAttribute(vq_main, cudaFuncAttributeMaxDynamicSharedMemorySize, SMEM_TOTAL);

    vq_prep<<<8, 128>>>(cb);
    vq_main<<<148, THREADS, SMEM_TOTAL>>>(x, cb, outq, outtok);
    vq_finalize<<<1, 1024>>>(outsc);
}